// round 14
// baseline (speedup 1.0000x reference)
#include <cuda_runtime.h>

// DegreePrediction: y[u] = sum_{s,t,v} (x*W_t)[s,t] * (W_r*r_zeros + r_const)[s,t,u,v]
// N = 80. Three 80^4 fp32 tensors (491.5 MB) streamed once.
//
// R14: the one untested cell. R7 (best, 77.4us kernel @ 6.42 TB/s) runs only
// 40/64 warps because its explicit prefetch pipeline costs 48 regs. R8's
// occ-6 test was confounded by 2x epilogue count (K=2). Here: K=4 (epilogue
// count == R7's 1600), plain fully-unrolled __ldcs loop (ptxas front-batches
// the immediate-offset LDG.128s itself, ~34-38 regs), __launch_bounds__(320,5)
// -> ~50 warps/SM. Epilogue/finalize identical to R7.
//
// Layout: slice = 1600 contiguous float4 = 5*320; iter j of each slice reads
// float4 tid+320*j -> u = tid/20 + 16*j (constant per thread,j).

#define NN 80
#define SLICE_F4 1600
#define SLICE_FLOATS (NN * NN)      // 6400
#define THREADS 320
#define J_ITERS 5
#define K_SLICES 4
#define NUM_BLOCKS ((NN * NN) / K_SLICES)   // 1600

__device__ float    g_scratch[NN];   // zero at load; kernel restores to zero
__device__ unsigned g_count;         // ditto

__device__ __forceinline__ unsigned atom_inc_acq_rel(unsigned* p) {
    unsigned old;
    asm volatile("atom.add.acq_rel.gpu.global.u32 %0, [%1], 1;"
                 : "=r"(old) : "l"(p) : "memory");
    return old;
}

__global__ __launch_bounds__(THREADS, 5)
void degree_pred_kernel(const float* __restrict__ x,
                        const float* __restrict__ r_zeros,
                        const float* __restrict__ r_const,
                        const float* __restrict__ weights_t,
                        const float* __restrict__ weights_r,
                        float* __restrict__ out)
{
    __shared__ float y_part[J_ITERS][THREADS];
    __shared__ bool is_last;
    const int tid = threadIdx.x;

    const int st0 = blockIdx.x * K_SLICES;

    float acc[J_ITERS];
#pragma unroll
    for (int j = 0; j < J_ITERS; j++) acc[j] = 0.0f;

#pragma unroll
    for (int k = 0; k < K_SLICES; k++) {
        const int st = st0 + k;
        const float a = __ldg(&x[st]) * __ldg(&weights_t[st]);
        const size_t base = (size_t)st * SLICE_FLOATS;
        const float4* __restrict__ rz = reinterpret_cast<const float4*>(r_zeros   + base);
        const float4* __restrict__ rc = reinterpret_cast<const float4*>(r_const   + base);
        const float4* __restrict__ wr = reinterpret_cast<const float4*>(weights_r + base);

#pragma unroll
        for (int j = 0; j < J_ITERS; j++) {
            const int p = tid + THREADS * j;
            const float4 z = __ldcs(&rz[p]);
            const float4 c = __ldcs(&rc[p]);
            const float4 w = __ldcs(&wr[p]);
            float t = (c.x + c.y) + (c.z + c.w);
            t = fmaf(w.x, z.x, t);
            t = fmaf(w.y, z.y, t);
            t = fmaf(w.z, z.z, t);
            t = fmaf(w.w, z.w, t);
            acc[j] = fmaf(a, t, acc[j]);
        }
    }

    // ---- epilogue (once per block): STS transpose + 80-thread gather ----
#pragma unroll
    for (int j = 0; j < J_ITERS; j++)
        y_part[j][tid] = acc[j];
    __syncthreads();

    if (tid < NN) {
        const int u = tid;
        const int j = u >> 4;            // u / 16
        const int b = (u & 15) * 20;     // first of 20 contributing threads
        float s = 0.0f;
#pragma unroll
        for (int d = 0; d < 20; d++)
            s += y_part[j][b + d];
        atomicAdd(&g_scratch[u], s);     // relaxed; published by acq_rel below
    }
    __syncthreads();

    // ---- last-block finalize ----
    if (tid == 0)
        is_last = (atom_inc_acq_rel(&g_count) == (unsigned)(NUM_BLOCKS - 1));
    __syncthreads();

    if (is_last) {
        if (tid < NN) {
            float v = __ldcg(&g_scratch[tid]);   // L2 read, coherent w/ atomics
            out[tid] = v;
            g_scratch[tid] = 0.0f;               // restore initial state
        }
        __syncthreads();
        if (tid == 0) g_count = 0u;              // restore initial state
    }
}

extern "C" void kernel_launch(void* const* d_in, const int* in_sizes, int n_in,
                              void* d_out, int out_size)
{
    const float* x         = (const float*)d_in[0];
    const float* r_zeros   = (const float*)d_in[1];
    const float* r_const   = (const float*)d_in[2];
    const float* weights_t = (const float*)d_in[3];
    const float* weights_r = (const float*)d_in[4];
    float* out = (float*)d_out;

    degree_pred_kernel<<<NUM_BLOCKS, THREADS>>>(x, r_zeros, r_const,
                                                weights_t, weights_r, out);
}

// round 15
// speedup vs baseline: 1.1717x; 1.1717x over previous
#include <cuda_runtime.h>

// DegreePrediction: y[u] = sum_{s,t,v} (x*W_t)[s,t] * (W_r*r_zeros + r_const)[s,t,u,v]
// N = 80. Three 80^4 fp32 tensors (491.5 MB) streamed once.
//
// R15: depth-2 explicit prefetch pipeline. Evidence chain: R7 (depth-1, 48
// regs, 40 warps) = 6.42 TB/s beats plain-loop at occ 85% (R14, 6.27) and
// occ 88% (R8, 6.07) -> guaranteed per-warp load depth is the lever, warps
// are not. R7 sustains ~2.3 LDG.128/warp in flight; depth-2 doubles that
// (6 per warp, ~720 sectors/SM at 3 blocks/SM) to probe whether the DRAM
// service ceiling lies above 6.42 TB/s. K=4, 1600 blocks, clean epilogue
// (STS transpose + gather + acq_rel counter finalize) exactly as R7.
//
// Layout: slice = 1600 contiguous float4 = 5*320; iter it (k=it/5, j=it%5)
// reads float4 tid + 320*j + 1600*k -> u = tid/20 + 16*j.

#define NN 80
#define SLICE_F4 1600
#define SLICE_FLOATS (NN * NN)      // 6400
#define THREADS 320
#define J_ITERS 5
#define K_SLICES 4
#define NITER (K_SLICES * J_ITERS)  // 20
#define NUM_BLOCKS ((NN * NN) / K_SLICES)   // 1600

__device__ float    g_scratch[NN];   // zero at load; kernel restores to zero
__device__ unsigned g_count;         // ditto

__device__ __forceinline__ unsigned atom_inc_acq_rel(unsigned* p) {
    unsigned old;
    asm volatile("atom.add.acq_rel.gpu.global.u32 %0, [%1], 1;"
                 : "=r"(old) : "l"(p) : "memory");
    return old;
}

__global__ __launch_bounds__(THREADS, 3)
void degree_pred_kernel(const float* __restrict__ x,
                        const float* __restrict__ r_zeros,
                        const float* __restrict__ r_const,
                        const float* __restrict__ weights_t,
                        const float* __restrict__ weights_r,
                        float* __restrict__ out)
{
    __shared__ float y_part[J_ITERS][THREADS];
    __shared__ bool is_last;
    const int tid = threadIdx.x;

    const int st0 = blockIdx.x * K_SLICES;

    float a[K_SLICES];
#pragma unroll
    for (int k = 0; k < K_SLICES; k++)
        a[k] = __ldg(&x[st0 + k]) * __ldg(&weights_t[st0 + k]);

    float acc[J_ITERS];
#pragma unroll
    for (int j = 0; j < J_ITERS; j++) acc[j] = 0.0f;

    const size_t base0 = (size_t)st0 * SLICE_FLOATS;
    const float4* __restrict__ rz = reinterpret_cast<const float4*>(r_zeros   + base0);
    const float4* __restrict__ rc = reinterpret_cast<const float4*>(r_const   + base0);
    const float4* __restrict__ wr = reinterpret_cast<const float4*>(weights_r + base0);

    // double-buffered prefetch registers, depth 2
    float4 zb[2], cb[2], wb[2];
    {
        const int p0 = tid;                   // it = 0
        const int p1 = tid + THREADS;         // it = 1
        zb[0] = __ldcs(&rz[p0]); cb[0] = __ldcs(&rc[p0]); wb[0] = __ldcs(&wr[p0]);
        zb[1] = __ldcs(&rz[p1]); cb[1] = __ldcs(&rc[p1]); wb[1] = __ldcs(&wr[p1]);
    }

#pragma unroll
    for (int it = 0; it < NITER; it++) {
        const int cur = it & 1;
        const int k = it / J_ITERS;
        const int j = it % J_ITERS;

        const float4 z = zb[cur];
        const float4 c = cb[cur];
        const float4 w = wb[cur];

        // refill this slot with iteration it+2 (compile-time immediate offset)
        if (it + 2 < NITER) {
            const int itn = it + 2;
            const int pn = tid + THREADS * (itn % J_ITERS) + SLICE_F4 * (itn / J_ITERS);
            zb[cur] = __ldcs(&rz[pn]);
            cb[cur] = __ldcs(&rc[pn]);
            wb[cur] = __ldcs(&wr[pn]);
        }

        float t = (c.x + c.y) + (c.z + c.w);
        t = fmaf(w.x, z.x, t);
        t = fmaf(w.y, z.y, t);
        t = fmaf(w.z, z.z, t);
        t = fmaf(w.w, z.w, t);
        acc[j] = fmaf(a[k], t, acc[j]);
    }

    // ---- epilogue (once per block): STS transpose + 80-thread gather ----
#pragma unroll
    for (int j = 0; j < J_ITERS; j++)
        y_part[j][tid] = acc[j];
    __syncthreads();

    if (tid < NN) {
        const int u = tid;
        const int j = u >> 4;            // u / 16
        const int b = (u & 15) * 20;     // first of 20 contributing threads
        float s = 0.0f;
#pragma unroll
        for (int d = 0; d < 20; d++)
            s += y_part[j][b + d];
        atomicAdd(&g_scratch[u], s);     // relaxed; published by acq_rel below
    }
    __syncthreads();

    // ---- last-block finalize ----
    if (tid == 0)
        is_last = (atom_inc_acq_rel(&g_count) == (unsigned)(NUM_BLOCKS - 1));
    __syncthreads();

    if (is_last) {
        if (tid < NN) {
            float v = __ldcg(&g_scratch[tid]);   // L2 read, coherent w/ atomics
            out[tid] = v;
            g_scratch[tid] = 0.0f;               // restore initial state
        }
        __syncthreads();
        if (tid == 0) g_count = 0u;              // restore initial state
    }
}

extern "C" void kernel_launch(void* const* d_in, const int* in_sizes, int n_in,
                              void* d_out, int out_size)
{
    const float* x         = (const float*)d_in[0];
    const float* r_zeros   = (const float*)d_in[1];
    const float* r_const   = (const float*)d_in[2];
    const float* weights_t = (const float*)d_in[3];
    const float* weights_r = (const float*)d_in[4];
    float* out = (float*)d_out;

    degree_pred_kernel<<<NUM_BLOCKS, THREADS>>>(x, r_zeros, r_const,
                                                weights_t, weights_r, out);
}